// round 12
// baseline (speedup 1.0000x reference)
#include <cuda_runtime.h>
#include <cuda_fp16.h>
#include <mma.h>
#include <cstdint>

using namespace nvcuda;

#define N_NODES 50000
#define NPAD    50048          // 391 * 128
#define N_EDGES 800000
#define E_TOT   (N_EDGES + N_NODES)
#define DIM     128
#define NUM_GRAPHS 512

// ---------------- scratch -------------------------------------------------
__device__ __align__(16) __half g_x  [NPAD * DIM];   // fp16 copy of x (pad rows stay 0)
__device__ __align__(16) __half g_b0 [NPAD * DIM];
__device__ __align__(16) __half g_b1 [NPAD * DIM];
__device__ __align__(16) __half g_hh [NPAD * DIM];   // GEMM output h (fp16)
__device__ __align__(16) float g_asA [N_NODES];
__device__ __align__(16) float g_adA [N_NODES];
__device__ __align__(16) float g_asB [N_NODES];
__device__ __align__(16) float g_adB [N_NODES];
__device__ __align__(16) float g_vs  [3 * DIM];      // W^T a_src per layer
__device__ __align__(16) float g_vd  [3 * DIM];      // W^T a_dst per layer
__device__ __align__(16) int   g_src [E_TOT];
__device__ __align__(16) int   g_dst [E_TOT];
__device__ __align__(16) int   g_rank[E_TOT];
__device__ int   g_cnt [N_NODES];
__device__ int   g_row [N_NODES + 1];
__device__ int   g_csrs[E_TOT];

// ---------------- CSR build (8 edges / thread for MLP) --------------------
__global__ void k_zero_cnt() {
    int i = blockIdx.x * blockDim.x + threadIdx.x;
    if (i < N_NODES) g_cnt[i] = 0;
}

__global__ void k_prep_count(const int* __restrict__ ei) {
    int t = blockIdx.x * blockDim.x + threadIdx.x;
    int i0 = t * 8;
    if (i0 >= E_TOT) return;
    int s[8], d[8], r[8];
    if (i0 < N_EDGES) {                 // N_EDGES % 8 == 0 -> no straddle
        int4 sa = *(const int4*)(ei + i0);
        int4 sb = *(const int4*)(ei + i0 + 4);
        int4 da = *(const int4*)(ei + N_EDGES + i0);
        int4 db = *(const int4*)(ei + N_EDGES + i0 + 4);
        s[0]=sa.x; s[1]=sa.y; s[2]=sa.z; s[3]=sa.w; s[4]=sb.x; s[5]=sb.y; s[6]=sb.z; s[7]=sb.w;
        d[0]=da.x; d[1]=da.y; d[2]=da.z; d[3]=da.w; d[4]=db.x; d[5]=db.y; d[6]=db.z; d[7]=db.w;
    } else {
        int n = i0 - N_EDGES;
#pragma unroll
        for (int q = 0; q < 8; q++) { s[q] = n + q; d[q] = n + q; }
    }
    *(int4*)(g_src + i0)     = make_int4(s[0], s[1], s[2], s[3]);
    *(int4*)(g_src + i0 + 4) = make_int4(s[4], s[5], s[6], s[7]);
    *(int4*)(g_dst + i0)     = make_int4(d[0], d[1], d[2], d[3]);
    *(int4*)(g_dst + i0 + 4) = make_int4(d[4], d[5], d[6], d[7]);
#pragma unroll
    for (int q = 0; q < 8; q++) r[q] = atomicAdd(&g_cnt[d[q]], 1);
    *(int4*)(g_rank + i0)     = make_int4(r[0], r[1], r[2], r[3]);
    *(int4*)(g_rank + i0 + 4) = make_int4(r[4], r[5], r[6], r[7]);
}

__global__ void k_scan() {          // single block, 1024 threads
    const int T = 1024;
    const int C = (N_NODES + T - 1) / T;
    __shared__ int ps[T];
    int t = threadIdx.x;
    int base = t * C;
    int s = 0;
    for (int i = 0; i < C; i++) { int n = base + i; if (n < N_NODES) s += g_cnt[n]; }
    ps[t] = s;
    __syncthreads();
    for (int off = 1; off < T; off <<= 1) {
        int v = (t >= off) ? ps[t - off] : 0;
        __syncthreads();
        ps[t] += v;
        __syncthreads();
    }
    int run = (t > 0) ? ps[t - 1] : 0;
    for (int i = 0; i < C; i++) {
        int n = base + i;
        if (n < N_NODES) { g_row[n] = run; run += g_cnt[n]; }
    }
    if (t == T - 1) g_row[N_NODES] = E_TOT;
}

// atomic-free fill: pos = row[d] + rank
__global__ void k_fill() {
    int t = blockIdx.x * blockDim.x + threadIdx.x;
    int i0 = t * 8;
    if (i0 >= E_TOT) return;
    int4 sa = *(const int4*)(g_src + i0);
    int4 sb = *(const int4*)(g_src + i0 + 4);
    int4 da = *(const int4*)(g_dst + i0);
    int4 db = *(const int4*)(g_dst + i0 + 4);
    int4 ra = *(const int4*)(g_rank + i0);
    int4 rb = *(const int4*)(g_rank + i0 + 4);
    int p0 = g_row[da.x] + ra.x;
    int p1 = g_row[da.y] + ra.y;
    int p2 = g_row[da.z] + ra.z;
    int p3 = g_row[da.w] + ra.w;
    int p4 = g_row[db.x] + rb.x;
    int p5 = g_row[db.y] + rb.y;
    int p6 = g_row[db.z] + rb.z;
    int p7 = g_row[db.w] + rb.w;
    g_csrs[p0] = sa.x; g_csrs[p1] = sa.y; g_csrs[p2] = sa.z; g_csrs[p3] = sa.w;
    g_csrs[p4] = sb.x; g_csrs[p5] = sb.y; g_csrs[p6] = sb.z; g_csrs[p7] = sb.w;
}

// ---------------- v = W^T a (per layer, src+dst) --------------------------
__global__ void k_matvec(const float* __restrict__ W0, const float* __restrict__ W1,
                         const float* __restrict__ W2,
                         const float* __restrict__ s0, const float* __restrict__ d0,
                         const float* __restrict__ s1, const float* __restrict__ d1,
                         const float* __restrict__ s2, const float* __restrict__ d2) {
    const float* W[3] = {W0, W1, W2};
    const float* A[6] = {s0, d0, s1, d1, s2, d2};
    int b = blockIdx.x;           // 0..5
    int l = b >> 1;
    const float* w = W[l];
    const float* a = A[b];
    int k = threadIdx.x;
    float s = 0.f;
#pragma unroll 4
    for (int j = 0; j < DIM; j++)
        s = fmaf(w[(size_t)j * DIM + k], a[j], s);
    if (b & 1) g_vd[l * DIM + k] = s;
    else       g_vs[l * DIM + k] = s;
}

// ---------------- copy x to fp16 padded buf + layer-0 attention dots ------
__global__ void k_copy_x(const float* __restrict__ x) {
    int gt = blockIdx.x * blockDim.x + threadIdx.x;
    int n = gt >> 5, lane = gt & 31;
    if (n >= N_NODES) return;
    float4 v = ((const float4*)(x + (size_t)n * DIM))[lane];
    __half2 h0 = __floats2half2_rn(v.x, v.y);
    __half2 h1 = __floats2half2_rn(v.z, v.w);
    uint2 u;
    u.x = *(unsigned*)&h0;
    u.y = *(unsigned*)&h1;
    ((uint2*)(g_x + (size_t)n * DIM))[lane] = u;
    float4 vs = ((const float4*)(g_vs))[lane];
    float4 vd = ((const float4*)(g_vd))[lane];
    float ps = v.x * vs.x + v.y * vs.y + v.z * vs.z + v.w * vs.w;
    float pd = v.x * vd.x + v.y * vd.y + v.z * vd.z + v.w * vd.w;
#pragma unroll
    for (int o = 16; o > 0; o >>= 1) {
        ps += __shfl_xor_sync(0xffffffffu, ps, o);
        pd += __shfl_xor_sync(0xffffffffu, pd, o);
    }
    if (lane == 0) { g_asA[n] = ps; g_adA[n] = pd; }
}

__global__ void k_zero(float* __restrict__ p, int n) {
    int i = blockIdx.x * blockDim.x + threadIdx.x;
    if (i < n) p[i] = 0.f;
}

// ---------------- fp16 tensor-core GEMM: H = act?(X) @ W^T ----------------
// Single-stage: whole 128x128 X tile + whole W in smem, one sync, 8 MMA steps.
#define XPADH 136                     // halves per smem row (272 B)
#define GEMM_SMEM (2 * 128 * XPADH * 2)   // 69632 B

__global__ void __launch_bounds__(256)
k_gemm(const __half* __restrict__ X, const float* __restrict__ W,
       __half* __restrict__ H, int apply_act) {
    extern __shared__ __align__(16) char smem[];
    __half* Xs = (__half*)smem;                       // [128][XPADH]
    __half* Ws = (__half*)smem + 128 * XPADH;         // [128][XPADH]
    int tid = threadIdx.x;
    int warp = tid >> 5, lane = tid & 31;
    int wm = warp & 3, wn = warp >> 2;
    int n0 = blockIdx.x * 128;

    // stage X: 128 rows x 128 halves; 8 x uint4 (8 halves) per thread
#pragma unroll
    for (int it = 0; it < 8; it++) {
        int u = tid + it * 256;              // 0..2047
        int row = u >> 4, c8 = (u & 15) * 8;
        uint4 v = *(const uint4*)(X + (size_t)(n0 + row) * DIM + c8);
        if (apply_act) {
            __half2* hp = (__half2*)&v;
#pragma unroll
            for (int q = 0; q < 4; q++) {
                float2 f = __half22float2(hp[q]);
                f.x = f.x > 0.f ? f.x : 0.01f * f.x;
                f.y = f.y > 0.f ? f.y : 0.01f * f.y;
                hp[q] = __floats2half2_rn(f.x, f.y);
            }
        }
        *(uint4*)(Xs + row * XPADH + c8) = v;
    }
    // stage W (fp32 -> fp16): 128x128 floats = 4096 float4 -> 16 iterations
#pragma unroll
    for (int it = 0; it < 16; it++) {
        int u = tid + it * 256;              // 0..4095
        int row = u >> 5, c4 = (u & 31) * 4;
        float4 w = *(const float4*)(W + (size_t)row * DIM + c4);
        __half2 w0 = __floats2half2_rn(w.x, w.y);
        __half2 w1 = __floats2half2_rn(w.z, w.w);
        uint2 uu;
        uu.x = *(unsigned*)&w0;
        uu.y = *(unsigned*)&w1;
        *(uint2*)(Ws + row * XPADH + c4) = uu;
    }
    __syncthreads();

    wmma::fragment<wmma::accumulator, 16, 16, 16, float> c[2][4];
#pragma unroll
    for (int i = 0; i < 2; i++)
#pragma unroll
        for (int j = 0; j < 4; j++) wmma::fill_fragment(c[i][j], 0.f);

#pragma unroll
    for (int kk = 0; kk < DIM; kk += 16) {
        wmma::fragment<wmma::matrix_a, 16, 16, 16, __half, wmma::row_major> a[2];
        wmma::fragment<wmma::matrix_b, 16, 16, 16, __half, wmma::col_major> b[4];
#pragma unroll
        for (int i = 0; i < 2; i++)
            wmma::load_matrix_sync(a[i], Xs + (wm * 32 + i * 16) * XPADH + kk, XPADH);
#pragma unroll
        for (int j = 0; j < 4; j++)
            wmma::load_matrix_sync(b[j], Ws + (wn * 64 + j * 16) * XPADH + kk, XPADH);
#pragma unroll
        for (int i = 0; i < 2; i++)
#pragma unroll
            for (int j = 0; j < 4; j++)
                wmma::mma_sync(c[i][j], a[i], b[j], c[i][j]);
    }
    __syncthreads();   // before smem reuse by epilogue

    // epilogue: per-warp smem region 32x64 fp32, convert to fp16, store
    float* epi = (float*)smem + warp * (32 * 64);
#pragma unroll
    for (int i = 0; i < 2; i++)
#pragma unroll
        for (int j = 0; j < 4; j++)
            wmma::store_matrix_sync(epi + i * 16 * 64 + j * 16, c[i][j], 64, wmma::mem_row_major);
    __syncwarp();
    {
        int row = lane;
        __half* hout = H + (size_t)(n0 + wm * 32 + row) * DIM + wn * 64;
        const float* src = epi + row * 64;
#pragma unroll
        for (int c0 = 0; c0 < 64; c0 += 8) {
            float4 f0 = *(const float4*)(src + c0);
            float4 f1 = *(const float4*)(src + c0 + 4);
            __half2 a0 = __floats2half2_rn(f0.x, f0.y);
            __half2 a1 = __floats2half2_rn(f0.z, f0.w);
            __half2 a2 = __floats2half2_rn(f1.x, f1.y);
            __half2 a3 = __floats2half2_rn(f1.z, f1.w);
            uint4 u;
            u.x = *(unsigned*)&a0; u.y = *(unsigned*)&a1;
            u.z = *(unsigned*)&a2; u.w = *(unsigned*)&a3;
            *(uint4*)(hout + c0) = u;
        }
    }
}

// ---------------- fused softmax + aggregate + next-layer dots -------------
__global__ void k_layer(void* __restrict__ outp, const int* __restrict__ batch,
                        const float* __restrict__ as_in, const float* __restrict__ ad_in,
                        float* __restrict__ as_out, float* __restrict__ ad_out,
                        const float* __restrict__ vs_n, const float* __restrict__ vd_n,
                        int act_next, int mode) {
    int gt = blockIdx.x * blockDim.x + threadIdx.x;
    int d = gt >> 5, lane = gt & 31;
    if (d >= N_NODES) return;
    int row0 = g_row[d], row1 = g_row[d + 1];
    float ad_d = ad_in[d];

    // pass 1: segment max (lanes split edges)
    float m = -1e30f;
    for (int i = row0 + lane; i < row1; i += 32) {
        float e = as_in[g_csrs[i]] + ad_d;
        e = e > 0.f ? e : 0.2f * e;
        m = fmaxf(m, e);
    }
#pragma unroll
    for (int o = 16; o > 0; o >>= 1)
        m = fmaxf(m, __shfl_xor_sync(0xffffffffu, m, o));

    // pass 2: z and weighted aggregate (fp16 gather, fp32 math)
    float z = 0.f;
    float4 acc = make_float4(0.f, 0.f, 0.f, 0.f);
    int i = row0;
    for (; i + 2 <= row1; i += 2) {
        int s0 = g_csrs[i], s1 = g_csrs[i + 1];
        float e0 = as_in[s0] + ad_d; e0 = e0 > 0.f ? e0 : 0.2f * e0;
        float e1 = as_in[s1] + ad_d; e1 = e1 > 0.f ? e1 : 0.2f * e1;
        float w0 = __expf(e0 - m), w1 = __expf(e1 - m);
        z += w0 + w1;
        uint2 u0 = ((const uint2*)(g_hh + (size_t)s0 * DIM))[lane];
        uint2 u1 = ((const uint2*)(g_hh + (size_t)s1 * DIM))[lane];
        float2 a0 = __half22float2(*(__half2*)&u0.x);
        float2 b0 = __half22float2(*(__half2*)&u0.y);
        float2 a1 = __half22float2(*(__half2*)&u1.x);
        float2 b1 = __half22float2(*(__half2*)&u1.y);
        acc.x = fmaf(w0, a0.x, fmaf(w1, a1.x, acc.x));
        acc.y = fmaf(w0, a0.y, fmaf(w1, a1.y, acc.y));
        acc.z = fmaf(w0, b0.x, fmaf(w1, b1.x, acc.z));
        acc.w = fmaf(w0, b0.y, fmaf(w1, b1.y, acc.w));
    }
    if (i < row1) {
        int s0 = g_csrs[i];
        float e0 = as_in[s0] + ad_d; e0 = e0 > 0.f ? e0 : 0.2f * e0;
        float w0 = __expf(e0 - m);
        z += w0;
        uint2 u0 = ((const uint2*)(g_hh + (size_t)s0 * DIM))[lane];
        float2 a0 = __half22float2(*(__half2*)&u0.x);
        float2 b0 = __half22float2(*(__half2*)&u0.y);
        acc.x = fmaf(w0, a0.x, acc.x);
        acc.y = fmaf(w0, a0.y, acc.y);
        acc.z = fmaf(w0, b0.x, acc.z);
        acc.w = fmaf(w0, b0.y, acc.w);
    }
    float inv = 1.f / (z + 1e-16f);
    acc.x *= inv; acc.y *= inv; acc.z *= inv; acc.w *= inv;

    if (mode == 1) {
        float* p = (float*)outp + (size_t)batch[d] * DIM + lane * 4;
        asm volatile("red.global.add.v4.f32 [%0], {%1,%2,%3,%4};"
                     :: "l"(p), "f"(acc.x), "f"(acc.y), "f"(acc.z), "f"(acc.w) : "memory");
    } else {
        __half2 h0 = __floats2half2_rn(acc.x, acc.y);
        __half2 h1 = __floats2half2_rn(acc.z, acc.w);
        uint2 u;
        u.x = *(unsigned*)&h0;
        u.y = *(unsigned*)&h1;
        ((uint2*)((__half*)outp + (size_t)d * DIM))[lane] = u;
        // next-layer attention dots from fp32 acc
        float4 t = acc;
        if (act_next) {
            t.x = t.x > 0.f ? t.x : 0.01f * t.x;
            t.y = t.y > 0.f ? t.y : 0.01f * t.y;
            t.z = t.z > 0.f ? t.z : 0.01f * t.z;
            t.w = t.w > 0.f ? t.w : 0.01f * t.w;
        }
        float4 vs = ((const float4*)vs_n)[lane];
        float4 vd = ((const float4*)vd_n)[lane];
        float ps = t.x * vs.x + t.y * vs.y + t.z * vs.z + t.w * vs.w;
        float pd = t.x * vd.x + t.y * vd.y + t.z * vd.z + t.w * vd.w;
#pragma unroll
        for (int o = 16; o > 0; o >>= 1) {
            ps += __shfl_xor_sync(0xffffffffu, ps, o);
            pd += __shfl_xor_sync(0xffffffffu, pd, o);
        }
        if (lane == 0) { as_out[d] = ps; ad_out[d] = pd; }
    }
}

// ---------------- stream/event for graph-fork (created at load time) ------
static cudaStream_t g_sb = nullptr;
static cudaEvent_t  g_evF = nullptr, g_evJ = nullptr;
namespace {
struct _GatInit {
    _GatInit() {
        cudaStreamCreateWithFlags(&g_sb, cudaStreamNonBlocking);
        cudaEventCreateWithFlags(&g_evF, cudaEventDisableTiming);
        cudaEventCreateWithFlags(&g_evJ, cudaEventDisableTiming);
    }
};
_GatInit _gat_init;
}

// ---------------- launch --------------------------------------------------
extern "C" void kernel_launch(void* const* d_in, const int* in_sizes, int n_in,
                              void* d_out, int out_size) {
    const float* x     = (const float*)d_in[0];
    const int*   ei    = (const int*)d_in[1];
    const int*   batch = (const int*)d_in[2];
    const float* W[3]   = {(const float*)d_in[3], (const float*)d_in[6], (const float*)d_in[9]};
    const float* As_[3] = {(const float*)d_in[4], (const float*)d_in[7], (const float*)d_in[10]};
    const float* Ad_[3] = {(const float*)d_in[5], (const float*)d_in[8], (const float*)d_in[11]};
    float* out = (float*)d_out;

    __half *xp, *b0, *b1, *hp;
    float *asA, *adA, *asB, *adB, *vsp, *vdp;
    cudaGetSymbolAddress((void**)&xp,  g_x);
    cudaGetSymbolAddress((void**)&b0,  g_b0);
    cudaGetSymbolAddress((void**)&b1,  g_b1);
    cudaGetSymbolAddress((void**)&hp,  g_hh);
    cudaGetSymbolAddress((void**)&asA, g_asA);
    cudaGetSymbolAddress((void**)&adA, g_adA);
    cudaGetSymbolAddress((void**)&asB, g_asB);
    cudaGetSymbolAddress((void**)&adB, g_adB);
    cudaGetSymbolAddress((void**)&vsp, g_vs);
    cudaGetSymbolAddress((void**)&vdp, g_vd);

    cudaFuncSetAttribute(k_gemm, cudaFuncAttributeMaxDynamicSharedMemorySize, GEMM_SMEM);

    // ---- fork: CSR build on side stream, concurrent with feature prep ----
    cudaEventRecord(g_evF, 0);
    cudaStreamWaitEvent(g_sb, g_evF, 0);
    k_zero_cnt<<<(N_NODES + 255) / 256, 256, 0, g_sb>>>();
    k_prep_count<<<(E_TOT / 8 + 255) / 256, 256, 0, g_sb>>>(ei);
    k_scan<<<1, 1024, 0, g_sb>>>();
    k_fill<<<(E_TOT / 8 + 255) / 256, 256, 0, g_sb>>>();
    cudaEventRecord(g_evJ, g_sb);

    // ---- main stream: weights prep + x copy + layer-0 GEMM --------------
    k_matvec<<<6, 128>>>(W[0], W[1], W[2], As_[0], Ad_[0], As_[1], Ad_[1], As_[2], Ad_[2]);
    k_copy_x<<<(N_NODES * 32 + 255) / 256, 256>>>(x);
    k_zero<<<(NUM_GRAPHS * DIM + 255) / 256, 256>>>(out, NUM_GRAPHS * DIM);
    k_gemm<<<NPAD / 128, 256, GEMM_SMEM>>>(xp, W[0], hp, 0);

    // ---- join -----------------------------------------------------------
    cudaStreamWaitEvent(0, g_evJ, 0);

    // layer 0: dots set A -> writes b0 + set B (dots for layer 1, no act)
    k_layer<<<(N_NODES * 32 + 255) / 256, 256>>>(b0, batch, asA, adA, asB, adB,
                                                 vsp + DIM, vdp + DIM, 0, 0);
    // layer 1: reads set B -> writes b1 + set A (dots for layer 2, act=leaky0.01)
    k_gemm<<<NPAD / 128, 256, GEMM_SMEM>>>(b0, W[1], hp, 0);
    k_layer<<<(N_NODES * 32 + 255) / 256, 256>>>(b1, batch, asB, adB, asA, adA,
                                                 vsp + 2 * DIM, vdp + 2 * DIM, 1, 0);
    // layer 2: GEMM applies act to input; reads set A; fused pool into out
    k_gemm<<<NPAD / 128, 256, GEMM_SMEM>>>(b1, W[2], hp, 1);
    k_layer<<<(N_NODES * 32 + 255) / 256, 256>>>(out, batch, asA, adA, nullptr, nullptr,
                                                 nullptr, nullptr, 0, 1);
}

// round 14
// speedup vs baseline: 1.3142x; 1.3142x over previous
#include <cuda_runtime.h>
#include <cuda_fp16.h>
#include <mma.h>
#include <cstdint>

using namespace nvcuda;

#define N_NODES 50000
#define NPAD    50048          // 391 * 128
#define N_EDGES 800000
#define E_TOT   (N_EDGES + N_NODES)
#define DIM     128
#define NUM_GRAPHS 512

// ---------------- scratch -------------------------------------------------
__device__ __align__(16) __half g_x  [NPAD * DIM];   // fp16 copy of x (pad rows stay 0)
__device__ __align__(16) __half g_b0 [NPAD * DIM];
__device__ __align__(16) __half g_b1 [NPAD * DIM];
__device__ __align__(16) __half g_hh [NPAD * DIM];   // GEMM output h (fp16)
__device__ __align__(16) float g_asA [N_NODES];
__device__ __align__(16) float g_adA [N_NODES];
__device__ __align__(16) float g_asB [N_NODES];
__device__ __align__(16) float g_adB [N_NODES];
__device__ __align__(16) float g_vs  [3 * DIM];      // W^T a_src per layer
__device__ __align__(16) float g_vd  [3 * DIM];      // W^T a_dst per layer
__device__ __align__(16) int   g_src [E_TOT];
__device__ __align__(16) int   g_dst [E_TOT];
__device__ __align__(16) int   g_rank[E_TOT];
__device__ int   g_cnt [N_NODES];
__device__ int   g_row [N_NODES + 1];
__device__ int   g_csrs[E_TOT];

// ---------------- CSR build (4 edges / thread) ----------------------------
__global__ void k_zero_cnt() {
    int i = blockIdx.x * blockDim.x + threadIdx.x;
    if (i < N_NODES) g_cnt[i] = 0;
}

// atomicAdd return = rank of edge within its dst segment
__global__ void k_prep_count(const int* __restrict__ ei) {
    int t = blockIdx.x * blockDim.x + threadIdx.x;
    int i0 = t * 4;
    if (i0 >= E_TOT) return;
    int4 s4, d4;
    if (i0 < N_EDGES) {                 // N_EDGES % 4 == 0 -> no straddle
        s4 = *(const int4*)(ei + i0);
        d4 = *(const int4*)(ei + N_EDGES + i0);
    } else {
        int n = i0 - N_EDGES;
        s4 = make_int4(n, n + 1, n + 2, n + 3);
        d4 = s4;
    }
    *(int4*)(g_src + i0) = s4;
    *(int4*)(g_dst + i0) = d4;
    int4 r4;
    r4.x = atomicAdd(&g_cnt[d4.x], 1);
    r4.y = atomicAdd(&g_cnt[d4.y], 1);
    r4.z = atomicAdd(&g_cnt[d4.z], 1);
    r4.w = atomicAdd(&g_cnt[d4.w], 1);
    *(int4*)(g_rank + i0) = r4;
}

__global__ void k_scan() {          // single block, 1024 threads
    const int T = 1024;
    const int C = (N_NODES + T - 1) / T;
    __shared__ int ps[T];
    int t = threadIdx.x;
    int base = t * C;
    int s = 0;
    for (int i = 0; i < C; i++) { int n = base + i; if (n < N_NODES) s += g_cnt[n]; }
    ps[t] = s;
    __syncthreads();
    for (int off = 1; off < T; off <<= 1) {
        int v = (t >= off) ? ps[t - off] : 0;
        __syncthreads();
        ps[t] += v;
        __syncthreads();
    }
    int run = (t > 0) ? ps[t - 1] : 0;
    for (int i = 0; i < C; i++) {
        int n = base + i;
        if (n < N_NODES) { g_row[n] = run; run += g_cnt[n]; }
    }
    if (t == T - 1) g_row[N_NODES] = E_TOT;
}

// atomic-free fill: pos = row[d] + rank
__global__ void k_fill() {
    int t = blockIdx.x * blockDim.x + threadIdx.x;
    int i0 = t * 4;
    if (i0 >= E_TOT) return;
    int4 s4 = *(const int4*)(g_src + i0);
    int4 d4 = *(const int4*)(g_dst + i0);
    int4 r4 = *(const int4*)(g_rank + i0);
    g_csrs[g_row[d4.x] + r4.x] = s4.x;
    g_csrs[g_row[d4.y] + r4.y] = s4.y;
    g_csrs[g_row[d4.z] + r4.z] = s4.z;
    g_csrs[g_row[d4.w] + r4.w] = s4.w;
}

// ---------------- v = W^T a (per layer, src+dst) --------------------------
__global__ void k_matvec(const float* __restrict__ W0, const float* __restrict__ W1,
                         const float* __restrict__ W2,
                         const float* __restrict__ s0, const float* __restrict__ d0,
                         const float* __restrict__ s1, const float* __restrict__ d1,
                         const float* __restrict__ s2, const float* __restrict__ d2) {
    const float* W[3] = {W0, W1, W2};
    const float* A[6] = {s0, d0, s1, d1, s2, d2};
    int b = blockIdx.x;           // 0..5
    int l = b >> 1;
    const float* w = W[l];
    const float* a = A[b];
    int k = threadIdx.x;
    float s = 0.f;
#pragma unroll 4
    for (int j = 0; j < DIM; j++)
        s = fmaf(w[(size_t)j * DIM + k], a[j], s);
    if (b & 1) g_vd[l * DIM + k] = s;
    else       g_vs[l * DIM + k] = s;
}

// ---------------- copy x to fp16 padded buf + layer-0 attention dots ------
__global__ void k_copy_x(const float* __restrict__ x) {
    int gt = blockIdx.x * blockDim.x + threadIdx.x;
    int n = gt >> 5, lane = gt & 31;
    if (n >= N_NODES) return;
    float4 v = ((const float4*)(x + (size_t)n * DIM))[lane];
    __half2 h0 = __floats2half2_rn(v.x, v.y);
    __half2 h1 = __floats2half2_rn(v.z, v.w);
    uint2 u;
    u.x = *(unsigned*)&h0;
    u.y = *(unsigned*)&h1;
    ((uint2*)(g_x + (size_t)n * DIM))[lane] = u;
    float4 vs = ((const float4*)(g_vs))[lane];
    float4 vd = ((const float4*)(g_vd))[lane];
    float ps = v.x * vs.x + v.y * vs.y + v.z * vs.z + v.w * vs.w;
    float pd = v.x * vd.x + v.y * vd.y + v.z * vd.z + v.w * vd.w;
#pragma unroll
    for (int o = 16; o > 0; o >>= 1) {
        ps += __shfl_xor_sync(0xffffffffu, ps, o);
        pd += __shfl_xor_sync(0xffffffffu, pd, o);
    }
    if (lane == 0) { g_asA[n] = ps; g_adA[n] = pd; }
}

__global__ void k_zero(float* __restrict__ p, int n) {
    int i = blockIdx.x * blockDim.x + threadIdx.x;
    if (i < n) p[i] = 0.f;
}

// ---------------- fp16 tensor-core GEMM: H = act?(X) @ W^T ----------------
// X fp16 [NPAD,128], W fp32 [128,128], H fp16. 256 thr = 8 warps (4m x 2n).
// Block tile 128x128, warp tile 32x64, smem-staged, BK=32.  (R8 known-good)
#define XPADH 48            // half elements per smem row (96B, 16B-aligned)
#define GEMM_SMEM 65536     // epilogue: 8 warps * 32*64 fp32

__global__ void __launch_bounds__(256)
k_gemm(const __half* __restrict__ X, const float* __restrict__ W,
       __half* __restrict__ H, int apply_act) {
    extern __shared__ __align__(16) char smem[];
    __half* Xs = (__half*)smem;                       // [128][XPADH]
    __half* Ws = (__half*)smem + 128 * XPADH;         // [128][XPADH]
    int tid = threadIdx.x;
    int warp = tid >> 5, lane = tid & 31;
    int wm = warp & 3, wn = warp >> 2;
    int n0 = blockIdx.x * 128;

    wmma::fragment<wmma::accumulator, 16, 16, 16, float> c[2][4];
#pragma unroll
    for (int i = 0; i < 2; i++)
#pragma unroll
        for (int j = 0; j < 4; j++) wmma::fill_fragment(c[i][j], 0.f);

    for (int k0 = 0; k0 < DIM; k0 += 32) {
        // stage X: 128 rows x 32 halves; 2 x uint4 (8 halves) per thread
#pragma unroll
        for (int it = 0; it < 2; it++) {
            int u = tid + it * 256;
            int row = u >> 2, c8 = (u & 3) * 8;
            uint4 v = *(const uint4*)(X + (size_t)(n0 + row) * DIM + k0 + c8);
            if (apply_act) {
                __half2* hp = (__half2*)&v;
#pragma unroll
                for (int q = 0; q < 4; q++) {
                    float2 f = __half22float2(hp[q]);
                    f.x = f.x > 0.f ? f.x : 0.01f * f.x;
                    f.y = f.y > 0.f ? f.y : 0.01f * f.y;
                    hp[q] = __floats2half2_rn(f.x, f.y);
                }
            }
            *(uint4*)(Xs + row * XPADH + c8) = v;
        }
        // stage W (fp32 -> fp16): 128 rows x 32 floats; 4 x float4 per thread
#pragma unroll
        for (int it = 0; it < 4; it++) {
            int u = tid + it * 256;
            int row = u >> 3, c4 = (u & 7) * 4;
            float4 w = *(const float4*)(W + (size_t)row * DIM + k0 + c4);
            __half2 w0 = __floats2half2_rn(w.x, w.y);
            __half2 w1 = __floats2half2_rn(w.z, w.w);
            uint2 uu;
            uu.x = *(unsigned*)&w0;
            uu.y = *(unsigned*)&w1;
            *(uint2*)(Ws + row * XPADH + c4) = uu;
        }
        __syncthreads();

#pragma unroll
        for (int kk = 0; kk < 32; kk += 16) {
            wmma::fragment<wmma::matrix_a, 16, 16, 16, __half, wmma::row_major> a[2];
            wmma::fragment<wmma::matrix_b, 16, 16, 16, __half, wmma::col_major> b[4];
#pragma unroll
            for (int i = 0; i < 2; i++)
                wmma::load_matrix_sync(a[i], Xs + (wm * 32 + i * 16) * XPADH + kk, XPADH);
#pragma unroll
            for (int j = 0; j < 4; j++)
                wmma::load_matrix_sync(b[j], Ws + (wn * 64 + j * 16) * XPADH + kk, XPADH);
#pragma unroll
            for (int i = 0; i < 2; i++)
#pragma unroll
                for (int j = 0; j < 4; j++)
                    wmma::mma_sync(c[i][j], a[i], b[j], c[i][j]);
        }
        __syncthreads();
    }

    // epilogue: per-warp smem region 32x64 fp32, convert to fp16, store
    float* epi = (float*)smem + warp * (32 * 64);
#pragma unroll
    for (int i = 0; i < 2; i++)
#pragma unroll
        for (int j = 0; j < 4; j++)
            wmma::store_matrix_sync(epi + i * 16 * 64 + j * 16, c[i][j], 64, wmma::mem_row_major);
    __syncwarp();
    {
        int row = lane;
        __half* hout = H + (size_t)(n0 + wm * 32 + row) * DIM + wn * 64;
        const float* src = epi + row * 64;
#pragma unroll
        for (int c0 = 0; c0 < 64; c0 += 8) {
            float4 f0 = *(const float4*)(src + c0);
            float4 f1 = *(const float4*)(src + c0 + 4);
            __half2 a0 = __floats2half2_rn(f0.x, f0.y);
            __half2 a1 = __floats2half2_rn(f0.z, f0.w);
            __half2 a2 = __floats2half2_rn(f1.x, f1.y);
            __half2 a3 = __floats2half2_rn(f1.z, f1.w);
            uint4 u;
            u.x = *(unsigned*)&a0; u.y = *(unsigned*)&a1;
            u.z = *(unsigned*)&a2; u.w = *(unsigned*)&a3;
            *(uint4*)(hout + c0) = u;
        }
    }
}

// ---------------- fused softmax + aggregate + next-layer dots -------------
// one warp per dst node; lane covers dims [4*lane, 4*lane+4).
// pass 2 unrolled 4 edges deep for MLP.
__global__ void k_layer(void* __restrict__ outp, const int* __restrict__ batch,
                        const float* __restrict__ as_in, const float* __restrict__ ad_in,
                        float* __restrict__ as_out, float* __restrict__ ad_out,
                        const float* __restrict__ vs_n, const float* __restrict__ vd_n,
                        int act_next, int mode) {
    int gt = blockIdx.x * blockDim.x + threadIdx.x;
    int d = gt >> 5, lane = gt & 31;
    if (d >= N_NODES) return;
    int row0 = g_row[d], row1 = g_row[d + 1];
    float ad_d = ad_in[d];

    // pass 1: segment max (lanes split edges)
    float m = -1e30f;
    for (int i = row0 + lane; i < row1; i += 32) {
        float e = as_in[g_csrs[i]] + ad_d;
        e = e > 0.f ? e : 0.2f * e;
        m = fmaxf(m, e);
    }
#pragma unroll
    for (int o = 16; o > 0; o >>= 1)
        m = fmaxf(m, __shfl_xor_sync(0xffffffffu, m, o));

    // pass 2: z and weighted aggregate (fp16 gather, fp32 math), 4-way unroll
    float z = 0.f;
    float4 acc = make_float4(0.f, 0.f, 0.f, 0.f);
    int i = row0;
    for (; i + 4 <= row1; i += 4) {
        int s0 = g_csrs[i], s1 = g_csrs[i + 1], s2 = g_csrs[i + 2], s3 = g_csrs[i + 3];
        // issue all gathers first (MLP=4 + 4 scalar loads)
        uint2 u0 = ((const uint2*)(g_hh + (size_t)s0 * DIM))[lane];
        uint2 u1 = ((const uint2*)(g_hh + (size_t)s1 * DIM))[lane];
        uint2 u2 = ((const uint2*)(g_hh + (size_t)s2 * DIM))[lane];
        uint2 u3 = ((const uint2*)(g_hh + (size_t)s3 * DIM))[lane];
        float e0 = as_in[s0] + ad_d; e0 = e0 > 0.f ? e0 : 0.2f * e0;
        float e1 = as_in[s1] + ad_d; e1 = e1 > 0.f ? e1 : 0.2f * e1;
        float e2 = as_in[s2] + ad_d; e2 = e2 > 0.f ? e2 : 0.2f * e2;
        float e3 = as_in[s3] + ad_d; e3 = e3 > 0.f ? e3 : 0.2f * e3;
        float w0 = __expf(e0 - m), w1 = __expf(e1 - m);
        float w2 = __expf(e2 - m), w3 = __expf(e3 - m);
        z += (w0 + w1) + (w2 + w3);
        float2 a0 = __half22float2(*(__half2*)&u0.x);
        float2 b0 = __half22float2(*(__half2*)&u0.y);
        float2 a1 = __half22float2(*(__half2*)&u1.x);
        float2 b1 = __half22float2(*(__half2*)&u1.y);
        float2 a2 = __half22float2(*(__half2*)&u2.x);
        float2 b2 = __half22float2(*(__half2*)&u2.y);
        float2 a3 = __half22float2(*(__half2*)&u3.x);
        float2 b3 = __half22float2(*(__half2*)&u3.y);
        acc.x = fmaf(w0, a0.x, fmaf(w1, a1.x, fmaf(w2, a2.x, fmaf(w3, a3.x, acc.x))));
        acc.y = fmaf(w0, a0.y, fmaf(w1, a1.y, fmaf(w2, a2.y, fmaf(w3, a3.y, acc.y))));
        acc.z = fmaf(w0, b0.x, fmaf(w1, b1.x, fmaf(w2, b2.x, fmaf(w3, b3.x, acc.z))));
        acc.w = fmaf(w0, b0.y, fmaf(w1, b1.y, fmaf(w2, b2.y, fmaf(w3, b3.y, acc.w))));
    }
    for (; i < row1; i++) {
        int s0 = g_csrs[i];
        uint2 u0 = ((const uint2*)(g_hh + (size_t)s0 * DIM))[lane];
        float e0 = as_in[s0] + ad_d; e0 = e0 > 0.f ? e0 : 0.2f * e0;
        float w0 = __expf(e0 - m);
        z += w0;
        float2 a0 = __half22float2(*(__half2*)&u0.x);
        float2 b0 = __half22float2(*(__half2*)&u0.y);
        acc.x = fmaf(w0, a0.x, acc.x);
        acc.y = fmaf(w0, a0.y, acc.y);
        acc.z = fmaf(w0, b0.x, acc.z);
        acc.w = fmaf(w0, b0.y, acc.w);
    }
    float inv = 1.f / (z + 1e-16f);
    acc.x *= inv; acc.y *= inv; acc.z *= inv; acc.w *= inv;

    if (mode == 1) {
        float* p = (float*)outp + (size_t)batch[d] * DIM + lane * 4;
        asm volatile("red.global.add.v4.f32 [%0], {%1,%2,%3,%4};"
                     :: "l"(p), "f"(acc.x), "f"(acc.y), "f"(acc.z), "f"(acc.w) : "memory");
    } else {
        __half2 h0 = __floats2half2_rn(acc.x, acc.y);
        __half2 h1 = __floats2half2_rn(acc.z, acc.w);
        uint2 u;
        u.x = *(unsigned*)&h0;
        u.y = *(unsigned*)&h1;
        ((uint2*)((__half*)outp + (size_t)d * DIM))[lane] = u;
        // next-layer attention dots from fp32 acc
        float4 t = acc;
        if (act_next) {
            t.x = t.x > 0.f ? t.x : 0.01f * t.x;
            t.y = t.y > 0.f ? t.y : 0.01f * t.y;
            t.z = t.z > 0.f ? t.z : 0.01f * t.z;
            t.w = t.w > 0.f ? t.w : 0.01f * t.w;
        }
        float4 vs = ((const float4*)vs_n)[lane];
        float4 vd = ((const float4*)vd_n)[lane];
        float ps = t.x * vs.x + t.y * vs.y + t.z * vs.z + t.w * vs.w;
        float pd = t.x * vd.x + t.y * vd.y + t.z * vd.z + t.w * vd.w;
#pragma unroll
        for (int o = 16; o > 0; o >>= 1) {
            ps += __shfl_xor_sync(0xffffffffu, ps, o);
            pd += __shfl_xor_sync(0xffffffffu, pd, o);
        }
        if (lane == 0) { as_out[d] = ps; ad_out[d] = pd; }
    }
}

// ---------------- launch (single stream, R8 ordering) ---------------------
extern "C" void kernel_launch(void* const* d_in, const int* in_sizes, int n_in,
                              void* d_out, int out_size) {
    const float* x     = (const float*)d_in[0];
    const int*   ei    = (const int*)d_in[1];
    const int*   batch = (const int*)d_in[2];
    const float* W[3]   = {(const float*)d_in[3], (const float*)d_in[6], (const float*)d_in[9]};
    const float* As_[3] = {(const float*)d_in[4], (const float*)d_in[7], (const float*)d_in[10]};
    const float* Ad_[3] = {(const float*)d_in[5], (const float*)d_in[8], (const float*)d_in[11]};
    float* out = (float*)d_out;

    __half *xp, *b0, *b1, *hp;
    float *asA, *adA, *asB, *adB, *vsp, *vdp;
    cudaGetSymbolAddress((void**)&xp,  g_x);
    cudaGetSymbolAddress((void**)&b0,  g_b0);
    cudaGetSymbolAddress((void**)&b1,  g_b1);
    cudaGetSymbolAddress((void**)&hp,  g_hh);
    cudaGetSymbolAddress((void**)&asA, g_asA);
    cudaGetSymbolAddress((void**)&adA, g_adA);
    cudaGetSymbolAddress((void**)&asB, g_asB);
    cudaGetSymbolAddress((void**)&adB, g_adB);
    cudaGetSymbolAddress((void**)&vsp, g_vs);
    cudaGetSymbolAddress((void**)&vdp, g_vd);

    cudaFuncSetAttribute(k_gemm, cudaFuncAttributeMaxDynamicSharedMemorySize, GEMM_SMEM);

    // CSR build (per launch; capturable, no allocation)
    k_zero_cnt<<<(N_NODES + 255) / 256, 256>>>();
    k_prep_count<<<(E_TOT / 4 + 255) / 256, 256>>>(ei);
    k_scan<<<1, 1024>>>();
    k_fill<<<(E_TOT / 4 + 255) / 256, 256>>>();

    k_matvec<<<6, 128>>>(W[0], W[1], W[2], As_[0], Ad_[0], As_[1], Ad_[1], As_[2], Ad_[2]);
    k_copy_x<<<(N_NODES * 32 + 255) / 256, 256>>>(x);
    k_zero<<<(NUM_GRAPHS * DIM + 255) / 256, 256>>>(out, NUM_GRAPHS * DIM);

    // layer 0: dots set A -> writes b0 + set B (dots for layer 1, no act)
    k_gemm<<<NPAD / 128, 256, GEMM_SMEM>>>(xp, W[0], hp, 0);
    k_layer<<<(N_NODES * 32 + 255) / 256, 256>>>(b0, batch, asA, adA, asB, adB,
                                                 vsp + DIM, vdp + DIM, 0, 0);
    // layer 1: reads set B -> writes b1 + set A (dots for layer 2, act=leaky0.01)
    k_gemm<<<NPAD / 128, 256, GEMM_SMEM>>>(b0, W[1], hp, 0);
    k_layer<<<(N_NODES * 32 + 255) / 256, 256>>>(b1, batch, asB, adB, asA, adA,
                                                 vsp + 2 * DIM, vdp + 2 * DIM, 1, 0);
    // layer 2: GEMM applies act to input; reads set A; fused pool into out
    k_gemm<<<NPAD / 128, 256, GEMM_SMEM>>>(b1, W[2], hp, 1);
    k_layer<<<(N_NODES * 32 + 255) / 256, 256>>>(out, batch, asA, adA, nullptr, nullptr,
                                                 nullptr, nullptr, 0, 1);
}

// round 16
// speedup vs baseline: 1.3351x; 1.0159x over previous
#include <cuda_runtime.h>
#include <cuda_fp16.h>
#include <mma.h>
#include <cstdint>

using namespace nvcuda;

#define N_NODES 50000
#define NPAD    50048          // 391 * 128
#define N_EDGES 800000
#define E_TOT   (N_EDGES + N_NODES)
#define DIM     128
#define NUM_GRAPHS 512

// ---------------- scratch -------------------------------------------------
__device__ __align__(16) __half g_x  [NPAD * DIM];   // fp16 copy of x (pad rows stay 0)
__device__ __align__(16) __half g_b0 [NPAD * DIM];
__device__ __align__(16) __half g_b1 [NPAD * DIM];
__device__ __align__(16) __half g_hh [NPAD * DIM];   // GEMM output h (fp16)
__device__ __align__(16) float g_asA [N_NODES];
__device__ __align__(16) float g_adA [N_NODES];
__device__ __align__(16) float g_asB [N_NODES];
__device__ __align__(16) float g_adB [N_NODES];
__device__ __align__(16) float g_vs  [3 * DIM];      // W^T a_src per layer
__device__ __align__(16) float g_vd  [3 * DIM];      // W^T a_dst per layer
__device__ __align__(16) int   g_src [E_TOT];
__device__ __align__(16) int   g_dst [E_TOT];
__device__ __align__(16) int   g_rank[E_TOT];
__device__ int   g_cnt [N_NODES];
__device__ int   g_row [N_NODES + 1];
__device__ int   g_csrs[E_TOT];

// ---------------- CSR build (4 edges / thread) ----------------------------
__global__ void k_zero_cnt() {
    int i = blockIdx.x * blockDim.x + threadIdx.x;
    if (i < N_NODES) g_cnt[i] = 0;
}

// atomicAdd return = rank of edge within its dst segment
__global__ void k_prep_count(const int* __restrict__ ei) {
    int t = blockIdx.x * blockDim.x + threadIdx.x;
    int i0 = t * 4;
    if (i0 >= E_TOT) return;
    int4 s4, d4;
    if (i0 < N_EDGES) {                 // N_EDGES % 4 == 0 -> no straddle
        s4 = *(const int4*)(ei + i0);
        d4 = *(const int4*)(ei + N_EDGES + i0);
    } else {
        int n = i0 - N_EDGES;
        s4 = make_int4(n, n + 1, n + 2, n + 3);
        d4 = s4;
    }
    *(int4*)(g_src + i0) = s4;
    *(int4*)(g_dst + i0) = d4;
    int4 r4;
    r4.x = atomicAdd(&g_cnt[d4.x], 1);
    r4.y = atomicAdd(&g_cnt[d4.y], 1);
    r4.z = atomicAdd(&g_cnt[d4.z], 1);
    r4.w = atomicAdd(&g_cnt[d4.w], 1);
    *(int4*)(g_rank + i0) = r4;
}

__global__ void k_scan() {          // single block, 1024 threads
    const int T = 1024;
    const int C = (N_NODES + T - 1) / T;
    __shared__ int ps[T];
    int t = threadIdx.x;
    int base = t * C;
    int s = 0;
    for (int i = 0; i < C; i++) { int n = base + i; if (n < N_NODES) s += g_cnt[n]; }
    ps[t] = s;
    __syncthreads();
    for (int off = 1; off < T; off <<= 1) {
        int v = (t >= off) ? ps[t - off] : 0;
        __syncthreads();
        ps[t] += v;
        __syncthreads();
    }
    int run = (t > 0) ? ps[t - 1] : 0;
    for (int i = 0; i < C; i++) {
        int n = base + i;
        if (n < N_NODES) { g_row[n] = run; run += g_cnt[n]; }
    }
    if (t == T - 1) g_row[N_NODES] = E_TOT;
}

// atomic-free fill: pos = row[d] + rank
__global__ void k_fill() {
    int t = blockIdx.x * blockDim.x + threadIdx.x;
    int i0 = t * 4;
    if (i0 >= E_TOT) return;
    int4 s4 = *(const int4*)(g_src + i0);
    int4 d4 = *(const int4*)(g_dst + i0);
    int4 r4 = *(const int4*)(g_rank + i0);
    g_csrs[g_row[d4.x] + r4.x] = s4.x;
    g_csrs[g_row[d4.y] + r4.y] = s4.y;
    g_csrs[g_row[d4.z] + r4.z] = s4.z;
    g_csrs[g_row[d4.w] + r4.w] = s4.w;
}

// ---------------- v = W^T a (per layer, src+dst) --------------------------
__global__ void k_matvec(const float* __restrict__ W0, const float* __restrict__ W1,
                         const float* __restrict__ W2,
                         const float* __restrict__ s0, const float* __restrict__ d0,
                         const float* __restrict__ s1, const float* __restrict__ d1,
                         const float* __restrict__ s2, const float* __restrict__ d2) {
    const float* W[3] = {W0, W1, W2};
    const float* A[6] = {s0, d0, s1, d1, s2, d2};
    int b = blockIdx.x;           // 0..5
    int l = b >> 1;
    const float* w = W[l];
    const float* a = A[b];
    int k = threadIdx.x;
    float s = 0.f;
#pragma unroll 4
    for (int j = 0; j < DIM; j++)
        s = fmaf(w[(size_t)j * DIM + k], a[j], s);
    if (b & 1) g_vd[l * DIM + k] = s;
    else       g_vs[l * DIM + k] = s;
}

// ---------------- copy x to fp16 padded buf + layer-0 attention dots ------
__global__ void k_copy_x(const float* __restrict__ x) {
    int gt = blockIdx.x * blockDim.x + threadIdx.x;
    int n = gt >> 5, lane = gt & 31;
    if (n >= N_NODES) return;
    float4 v = ((const float4*)(x + (size_t)n * DIM))[lane];
    __half2 h0 = __floats2half2_rn(v.x, v.y);
    __half2 h1 = __floats2half2_rn(v.z, v.w);
    uint2 u;
    u.x = *(unsigned*)&h0;
    u.y = *(unsigned*)&h1;
    ((uint2*)(g_x + (size_t)n * DIM))[lane] = u;
    float4 vs = ((const float4*)(g_vs))[lane];
    float4 vd = ((const float4*)(g_vd))[lane];
    float ps = v.x * vs.x + v.y * vs.y + v.z * vs.z + v.w * vs.w;
    float pd = v.x * vd.x + v.y * vd.y + v.z * vd.z + v.w * vd.w;
#pragma unroll
    for (int o = 16; o > 0; o >>= 1) {
        ps += __shfl_xor_sync(0xffffffffu, ps, o);
        pd += __shfl_xor_sync(0xffffffffu, pd, o);
    }
    if (lane == 0) { g_asA[n] = ps; g_adA[n] = pd; }
}

__global__ void k_zero(float* __restrict__ p, int n) {
    int i = blockIdx.x * blockDim.x + threadIdx.x;
    if (i < n) p[i] = 0.f;
}

// ---------------- fp16 tensor-core GEMM: H = act?(X) @ W^T ----------------
// X fp16 [NPAD,128], W fp32 [128,128], H fp16. 256 thr = 8 warps (4m x 2n).
// Block tile 128x128, warp tile 32x64, smem-staged, BK=32.  (R8 known-good)
#define XPADH 48            // half elements per smem row (96B, 16B-aligned)
#define GEMM_SMEM 65536     // epilogue: 8 warps * 32*64 fp32

__global__ void __launch_bounds__(256)
k_gemm(const __half* __restrict__ X, const float* __restrict__ W,
       __half* __restrict__ H, int apply_act) {
    extern __shared__ __align__(16) char smem[];
    __half* Xs = (__half*)smem;                       // [128][XPADH]
    __half* Ws = (__half*)smem + 128 * XPADH;         // [128][XPADH]
    int tid = threadIdx.x;
    int warp = tid >> 5, lane = tid & 31;
    int wm = warp & 3, wn = warp >> 2;
    int n0 = blockIdx.x * 128;

    wmma::fragment<wmma::accumulator, 16, 16, 16, float> c[2][4];
#pragma unroll
    for (int i = 0; i < 2; i++)
#pragma unroll
        for (int j = 0; j < 4; j++) wmma::fill_fragment(c[i][j], 0.f);

    for (int k0 = 0; k0 < DIM; k0 += 32) {
        // stage X: 128 rows x 32 halves; 2 x uint4 (8 halves) per thread
#pragma unroll
        for (int it = 0; it < 2; it++) {
            int u = tid + it * 256;
            int row = u >> 2, c8 = (u & 3) * 8;
            uint4 v = *(const uint4*)(X + (size_t)(n0 + row) * DIM + k0 + c8);
            if (apply_act) {
                __half2* hp = (__half2*)&v;
#pragma unroll
                for (int q = 0; q < 4; q++) {
                    float2 f = __half22float2(hp[q]);
                    f.x = f.x > 0.f ? f.x : 0.01f * f.x;
                    f.y = f.y > 0.f ? f.y : 0.01f * f.y;
                    hp[q] = __floats2half2_rn(f.x, f.y);
                }
            }
            *(uint4*)(Xs + row * XPADH + c8) = v;
        }
        // stage W (fp32 -> fp16): 128 rows x 32 floats; 4 x float4 per thread
#pragma unroll
        for (int it = 0; it < 4; it++) {
            int u = tid + it * 256;
            int row = u >> 3, c4 = (u & 7) * 4;
            float4 w = *(const float4*)(W + (size_t)row * DIM + k0 + c4);
            __half2 w0 = __floats2half2_rn(w.x, w.y);
            __half2 w1 = __floats2half2_rn(w.z, w.w);
            uint2 uu;
            uu.x = *(unsigned*)&w0;
            uu.y = *(unsigned*)&w1;
            *(uint2*)(Ws + row * XPADH + c4) = uu;
        }
        __syncthreads();

#pragma unroll
        for (int kk = 0; kk < 32; kk += 16) {
            wmma::fragment<wmma::matrix_a, 16, 16, 16, __half, wmma::row_major> a[2];
            wmma::fragment<wmma::matrix_b, 16, 16, 16, __half, wmma::col_major> b[4];
#pragma unroll
            for (int i = 0; i < 2; i++)
                wmma::load_matrix_sync(a[i], Xs + (wm * 32 + i * 16) * XPADH + kk, XPADH);
#pragma unroll
            for (int j = 0; j < 4; j++)
                wmma::load_matrix_sync(b[j], Ws + (wn * 64 + j * 16) * XPADH + kk, XPADH);
#pragma unroll
            for (int i = 0; i < 2; i++)
#pragma unroll
                for (int j = 0; j < 4; j++)
                    wmma::mma_sync(c[i][j], a[i], b[j], c[i][j]);
        }
        __syncthreads();
    }

    // epilogue: per-warp smem region 32x64 fp32, convert to fp16, store
    float* epi = (float*)smem + warp * (32 * 64);
#pragma unroll
    for (int i = 0; i < 2; i++)
#pragma unroll
        for (int j = 0; j < 4; j++)
            wmma::store_matrix_sync(epi + i * 16 * 64 + j * 16, c[i][j], 64, wmma::mem_row_major);
    __syncwarp();
    {
        int row = lane;
        __half* hout = H + (size_t)(n0 + wm * 32 + row) * DIM + wn * 64;
        const float* src = epi + row * 64;
#pragma unroll
        for (int c0 = 0; c0 < 64; c0 += 8) {
            float4 f0 = *(const float4*)(src + c0);
            float4 f1 = *(const float4*)(src + c0 + 4);
            __half2 a0 = __floats2half2_rn(f0.x, f0.y);
            __half2 a1 = __floats2half2_rn(f0.z, f0.w);
            __half2 a2 = __floats2half2_rn(f1.x, f1.y);
            __half2 a3 = __floats2half2_rn(f1.z, f1.w);
            uint4 u;
            u.x = *(unsigned*)&a0; u.y = *(unsigned*)&a1;
            u.z = *(unsigned*)&a2; u.w = *(unsigned*)&a3;
            *(uint4*)(hout + c0) = u;
        }
    }
}

// ---------------- fused softmax + aggregate + next-layer dots -------------
// HALF-WARP per dst node: 16 lanes, each covers dims [8*hl, 8*hl+8) as uint4
// of fp16 (LDG.128 gathers). 4-way edge unroll. Reductions over 16 lanes.
__global__ void k_layer(void* __restrict__ outp, const int* __restrict__ batch,
                        const float* __restrict__ as_in, const float* __restrict__ ad_in,
                        float* __restrict__ as_out, float* __restrict__ ad_out,
                        const float* __restrict__ vs_n, const float* __restrict__ vd_n,
                        int act_next, int mode) {
    int gt = blockIdx.x * blockDim.x + threadIdx.x;
    int d = gt >> 4, hl = gt & 15;
    if (d >= N_NODES) return;
    int row0 = g_row[d], row1 = g_row[d + 1];
    float ad_d = ad_in[d];

    // pass 1: segment max (16 lanes split edges)
    float m = -1e30f;
    for (int i = row0 + hl; i < row1; i += 16) {
        float e = as_in[g_csrs[i]] + ad_d;
        e = e > 0.f ? e : 0.2f * e;
        m = fmaxf(m, e);
    }
#pragma unroll
    for (int o = 8; o > 0; o >>= 1)
        m = fmaxf(m, __shfl_xor_sync(0xffffffffu, m, o));

    // pass 2: z and weighted aggregate, 4-way edge unroll, uint4 gathers
    float z = 0.f;
    float acc[8];
#pragma unroll
    for (int q = 0; q < 8; q++) acc[q] = 0.f;

    int i = row0;
    for (; i + 4 <= row1; i += 4) {
        int s0 = g_csrs[i], s1 = g_csrs[i + 1], s2 = g_csrs[i + 2], s3 = g_csrs[i + 3];
        uint4 u0 = ((const uint4*)(g_hh + (size_t)s0 * DIM))[hl];
        uint4 u1 = ((const uint4*)(g_hh + (size_t)s1 * DIM))[hl];
        uint4 u2 = ((const uint4*)(g_hh + (size_t)s2 * DIM))[hl];
        uint4 u3 = ((const uint4*)(g_hh + (size_t)s3 * DIM))[hl];
        float e0 = as_in[s0] + ad_d; e0 = e0 > 0.f ? e0 : 0.2f * e0;
        float e1 = as_in[s1] + ad_d; e1 = e1 > 0.f ? e1 : 0.2f * e1;
        float e2 = as_in[s2] + ad_d; e2 = e2 > 0.f ? e2 : 0.2f * e2;
        float e3 = as_in[s3] + ad_d; e3 = e3 > 0.f ? e3 : 0.2f * e3;
        float w0 = __expf(e0 - m), w1 = __expf(e1 - m);
        float w2 = __expf(e2 - m), w3 = __expf(e3 - m);
        z += (w0 + w1) + (w2 + w3);
        const unsigned* p0 = &u0.x;
        const unsigned* p1 = &u1.x;
        const unsigned* p2 = &u2.x;
        const unsigned* p3 = &u3.x;
#pragma unroll
        for (int q = 0; q < 4; q++) {
            float2 f0 = __half22float2(*(__half2*)&p0[q]);
            float2 f1 = __half22float2(*(__half2*)&p1[q]);
            float2 f2 = __half22float2(*(__half2*)&p2[q]);
            float2 f3 = __half22float2(*(__half2*)&p3[q]);
            acc[2*q]   = fmaf(w0, f0.x, fmaf(w1, f1.x, fmaf(w2, f2.x, fmaf(w3, f3.x, acc[2*q]))));
            acc[2*q+1] = fmaf(w0, f0.y, fmaf(w1, f1.y, fmaf(w2, f2.y, fmaf(w3, f3.y, acc[2*q+1]))));
        }
    }
    for (; i < row1; i++) {
        int s0 = g_csrs[i];
        uint4 u0 = ((const uint4*)(g_hh + (size_t)s0 * DIM))[hl];
        float e0 = as_in[s0] + ad_d; e0 = e0 > 0.f ? e0 : 0.2f * e0;
        float w0 = __expf(e0 - m);
        z += w0;
        const unsigned* p0 = &u0.x;
#pragma unroll
        for (int q = 0; q < 4; q++) {
            float2 f0 = __half22float2(*(__half2*)&p0[q]);
            acc[2*q]   = fmaf(w0, f0.x, acc[2*q]);
            acc[2*q+1] = fmaf(w0, f0.y, acc[2*q+1]);
        }
    }
    float inv = 1.f / (z + 1e-16f);
#pragma unroll
    for (int q = 0; q < 8; q++) acc[q] *= inv;

    if (mode == 1) {
        float* p = (float*)outp + (size_t)batch[d] * DIM + hl * 8;
        asm volatile("red.global.add.v4.f32 [%0], {%1,%2,%3,%4};"
                     :: "l"(p), "f"(acc[0]), "f"(acc[1]), "f"(acc[2]), "f"(acc[3]) : "memory");
        asm volatile("red.global.add.v4.f32 [%0], {%1,%2,%3,%4};"
                     :: "l"(p + 4), "f"(acc[4]), "f"(acc[5]), "f"(acc[6]), "f"(acc[7]) : "memory");
    } else {
        __half2 h0 = __floats2half2_rn(acc[0], acc[1]);
        __half2 h1 = __floats2half2_rn(acc[2], acc[3]);
        __half2 h2 = __floats2half2_rn(acc[4], acc[5]);
        __half2 h3 = __floats2half2_rn(acc[6], acc[7]);
        uint4 u;
        u.x = *(unsigned*)&h0; u.y = *(unsigned*)&h1;
        u.z = *(unsigned*)&h2; u.w = *(unsigned*)&h3;
        ((uint4*)((__half*)outp + (size_t)d * DIM))[hl] = u;
        // next-layer attention dots from fp32 acc
        float t[8];
#pragma unroll
        for (int q = 0; q < 8; q++) {
            float v = acc[q];
            t[q] = act_next ? (v > 0.f ? v : 0.01f * v) : v;
        }
        float4 vs0 = ((const float4*)vs_n)[hl * 2];
        float4 vs1 = ((const float4*)vs_n)[hl * 2 + 1];
        float4 vd0 = ((const float4*)vd_n)[hl * 2];
        float4 vd1 = ((const float4*)vd_n)[hl * 2 + 1];
        float ps = t[0]*vs0.x + t[1]*vs0.y + t[2]*vs0.z + t[3]*vs0.w
                 + t[4]*vs1.x + t[5]*vs1.y + t[6]*vs1.z + t[7]*vs1.w;
        float pd = t[0]*vd0.x + t[1]*vd0.y + t[2]*vd0.z + t[3]*vd0.w
                 + t[4]*vd1.x + t[5]*vd1.y + t[6]*vd1.z + t[7]*vd1.w;
#pragma unroll
        for (int o = 8; o > 0; o >>= 1) {
            ps += __shfl_xor_sync(0xffffffffu, ps, o);
            pd += __shfl_xor_sync(0xffffffffu, pd, o);
        }
        if (hl == 0) { as_out[d] = ps; ad_out[d] = pd; }
    }
}

// ---------------- launch (single stream, R8 ordering) ---------------------
extern "C" void kernel_launch(void* const* d_in, const int* in_sizes, int n_in,
                              void* d_out, int out_size) {
    const float* x     = (const float*)d_in[0];
    const int*   ei    = (const int*)d_in[1];
    const int*   batch = (const int*)d_in[2];
    const float* W[3]   = {(const float*)d_in[3], (const float*)d_in[6], (const float*)d_in[9]};
    const float* As_[3] = {(const float*)d_in[4], (const float*)d_in[7], (const float*)d_in[10]};
    const float* Ad_[3] = {(const float*)d_in[5], (const float*)d_in[8], (const float*)d_in[11]};
    float* out = (float*)d_out;

    __half *xp, *b0, *b1, *hp;
    float *asA, *adA, *asB, *adB, *vsp, *vdp;
    cudaGetSymbolAddress((void**)&xp,  g_x);
    cudaGetSymbolAddress((void**)&b0,  g_b0);
    cudaGetSymbolAddress((void**)&b1,  g_b1);
    cudaGetSymbolAddress((void**)&hp,  g_hh);
    cudaGetSymbolAddress((void**)&asA, g_asA);
    cudaGetSymbolAddress((void**)&adA, g_adA);
    cudaGetSymbolAddress((void**)&asB, g_asB);
    cudaGetSymbolAddress((void**)&adB, g_adB);
    cudaGetSymbolAddress((void**)&vsp, g_vs);
    cudaGetSymbolAddress((void**)&vdp, g_vd);

    cudaFuncSetAttribute(k_gemm, cudaFuncAttributeMaxDynamicSharedMemorySize, GEMM_SMEM);

    // CSR build (per launch; capturable, no allocation)
    k_zero_cnt<<<(N_NODES + 255) / 256, 256>>>();
    k_prep_count<<<(E_TOT / 4 + 255) / 256, 256>>>(ei);
    k_scan<<<1, 1024>>>();
    k_fill<<<(E_TOT / 4 + 255) / 256, 256>>>();

    k_matvec<<<6, 128>>>(W[0], W[1], W[2], As_[0], Ad_[0], As_[1], Ad_[1], As_[2], Ad_[2]);
    k_copy_x<<<(N_NODES * 32 + 255) / 256, 256>>>(x);
    k_zero<<<(NUM_GRAPHS * DIM + 255) / 256, 256>>>(out, NUM_GRAPHS * DIM);

    // layer 0: dots set A -> writes b0 + set B (dots for layer 1, no act)
    k_gemm<<<NPAD / 128, 256, GEMM_SMEM>>>(xp, W[0], hp, 0);
    k_layer<<<(N_NODES * 16 + 255) / 256, 256>>>(b0, batch, asA, adA, asB, adB,
                                                 vsp + DIM, vdp + DIM, 0, 0);
    // layer 1: reads set B -> writes b1 + set A (dots for layer 2, act=leaky0.01)
    k_gemm<<<NPAD / 128, 256, GEMM_SMEM>>>(b0, W[1], hp, 0);
    k_layer<<<(N_NODES * 16 + 255) / 256, 256>>>(b1, batch, asB, adB, asA, adA,
                                                 vsp + 2 * DIM, vdp + 2 * DIM, 1, 0);
    // layer 2: GEMM applies act to input; reads set A; fused pool into out
    k_gemm<<<NPAD / 128, 256, GEMM_SMEM>>>(b1, W[2], hp, 1);
    k_layer<<<(N_NODES * 16 + 255) / 256, 256>>>(out, batch, asA, adA, nullptr, nullptr,
                                                 nullptr, nullptr, 0, 1);
}

// round 17
// speedup vs baseline: 1.3748x; 1.0297x over previous
#include <cuda_runtime.h>
#include <cuda_fp16.h>
#include <mma.h>
#include <cstdint>

using namespace nvcuda;

#define N_NODES 50000
#define NPAD    50048          // 391 * 128
#define N_EDGES 800000
#define E_TOT   (N_EDGES + N_NODES)
#define DIM     128
#define NUM_GRAPHS 512

// ---------------- scratch -------------------------------------------------
__device__ __align__(16) __half g_x  [NPAD * DIM];   // fp16 copy of x (pad rows stay 0)
__device__ __align__(16) __half g_b0 [NPAD * DIM];
__device__ __align__(16) __half g_b1 [NPAD * DIM];
__device__ __align__(16) __half g_hh [NPAD * DIM];   // GEMM output h (fp16)
__device__ __align__(16) float g_asA [N_NODES];
__device__ __align__(16) float g_adA [N_NODES];
__device__ __align__(16) float g_asB [N_NODES];
__device__ __align__(16) float g_adB [N_NODES];
__device__ __align__(16) float g_vs  [3 * DIM];      // W^T a_src per layer
__device__ __align__(16) float g_vd  [3 * DIM];      // W^T a_dst per layer
__device__ __align__(16) int   g_src [E_TOT];
__device__ __align__(16) int   g_dst [E_TOT];
__device__ __align__(16) int   g_rank[E_TOT];
__device__ int   g_cnt [N_NODES];
__device__ int   g_row [N_NODES + 1];
__device__ int   g_csrs[E_TOT];

// ---------------- CSR build (4 edges / thread) ----------------------------
__global__ void k_zero_cnt() {
    int i = blockIdx.x * blockDim.x + threadIdx.x;
    if (i < N_NODES) g_cnt[i] = 0;
}

// atomicAdd return = rank of edge within its dst segment
__global__ void k_prep_count(const int* __restrict__ ei) {
    int t = blockIdx.x * blockDim.x + threadIdx.x;
    int i0 = t * 4;
    if (i0 >= E_TOT) return;
    int4 s4, d4;
    if (i0 < N_EDGES) {                 // N_EDGES % 4 == 0 -> no straddle
        s4 = *(const int4*)(ei + i0);
        d4 = *(const int4*)(ei + N_EDGES + i0);
    } else {
        int n = i0 - N_EDGES;
        s4 = make_int4(n, n + 1, n + 2, n + 3);
        d4 = s4;
    }
    *(int4*)(g_src + i0) = s4;
    *(int4*)(g_dst + i0) = d4;
    int4 r4;
    r4.x = atomicAdd(&g_cnt[d4.x], 1);
    r4.y = atomicAdd(&g_cnt[d4.y], 1);
    r4.z = atomicAdd(&g_cnt[d4.z], 1);
    r4.w = atomicAdd(&g_cnt[d4.w], 1);
    *(int4*)(g_rank + i0) = r4;
}

__global__ void k_scan() {          // single block, 1024 threads
    const int T = 1024;
    const int C = (N_NODES + T - 1) / T;
    __shared__ int ps[T];
    int t = threadIdx.x;
    int base = t * C;
    int s = 0;
    for (int i = 0; i < C; i++) { int n = base + i; if (n < N_NODES) s += g_cnt[n]; }
    ps[t] = s;
    __syncthreads();
    for (int off = 1; off < T; off <<= 1) {
        int v = (t >= off) ? ps[t - off] : 0;
        __syncthreads();
        ps[t] += v;
        __syncthreads();
    }
    int run = (t > 0) ? ps[t - 1] : 0;
    for (int i = 0; i < C; i++) {
        int n = base + i;
        if (n < N_NODES) { g_row[n] = run; run += g_cnt[n]; }
    }
    if (t == T - 1) g_row[N_NODES] = E_TOT;
}

// atomic-free fill: pos = row[d] + rank
__global__ void k_fill() {
    int t = blockIdx.x * blockDim.x + threadIdx.x;
    int i0 = t * 4;
    if (i0 >= E_TOT) return;
    int4 s4 = *(const int4*)(g_src + i0);
    int4 d4 = *(const int4*)(g_dst + i0);
    int4 r4 = *(const int4*)(g_rank + i0);
    g_csrs[g_row[d4.x] + r4.x] = s4.x;
    g_csrs[g_row[d4.y] + r4.y] = s4.y;
    g_csrs[g_row[d4.z] + r4.z] = s4.z;
    g_csrs[g_row[d4.w] + r4.w] = s4.w;
}

// ---------------- v = W^T a (per layer, src+dst) --------------------------
__global__ void k_matvec(const float* __restrict__ W0, const float* __restrict__ W1,
                         const float* __restrict__ W2,
                         const float* __restrict__ s0, const float* __restrict__ d0,
                         const float* __restrict__ s1, const float* __restrict__ d1,
                         const float* __restrict__ s2, const float* __restrict__ d2) {
    const float* W[3] = {W0, W1, W2};
    const float* A[6] = {s0, d0, s1, d1, s2, d2};
    int b = blockIdx.x;           // 0..5
    int l = b >> 1;
    const float* w = W[l];
    const float* a = A[b];
    int k = threadIdx.x;
    float s = 0.f;
#pragma unroll 4
    for (int j = 0; j < DIM; j++)
        s = fmaf(w[(size_t)j * DIM + k], a[j], s);
    if (b & 1) g_vd[l * DIM + k] = s;
    else       g_vs[l * DIM + k] = s;
}

// ---------------- copy x to fp16 padded buf + layer-0 attention dots ------
__global__ void k_copy_x(const float* __restrict__ x) {
    int gt = blockIdx.x * blockDim.x + threadIdx.x;
    int n = gt >> 5, lane = gt & 31;
    if (n >= N_NODES) return;
    float4 v = ((const float4*)(x + (size_t)n * DIM))[lane];
    __half2 h0 = __floats2half2_rn(v.x, v.y);
    __half2 h1 = __floats2half2_rn(v.z, v.w);
    uint2 u;
    u.x = *(unsigned*)&h0;
    u.y = *(unsigned*)&h1;
    ((uint2*)(g_x + (size_t)n * DIM))[lane] = u;
    float4 vs = ((const float4*)(g_vs))[lane];
    float4 vd = ((const float4*)(g_vd))[lane];
    float ps = v.x * vs.x + v.y * vs.y + v.z * vs.z + v.w * vs.w;
    float pd = v.x * vd.x + v.y * vd.y + v.z * vd.z + v.w * vd.w;
#pragma unroll
    for (int o = 16; o > 0; o >>= 1) {
        ps += __shfl_xor_sync(0xffffffffu, ps, o);
        pd += __shfl_xor_sync(0xffffffffu, pd, o);
    }
    if (lane == 0) { g_asA[n] = ps; g_adA[n] = pd; }
}

__global__ void k_zero(float* __restrict__ p, int n) {
    int i = blockIdx.x * blockDim.x + threadIdx.x;
    if (i < n) p[i] = 0.f;
}

// ---------------- fp16 tensor-core GEMM: H = act?(X) @ W^T ----------------
// X fp16 [NPAD,128], W fp32 [128,128], H fp16. 256 thr = 8 warps (4m x 2n).
// Block tile 128x128, warp tile 32x64, smem-staged, BK=32.  (R8 known-good)
#define XPADH 48            // half elements per smem row (96B, 16B-aligned)
#define GEMM_SMEM 65536     // epilogue: 8 warps * 32*64 fp32

__global__ void __launch_bounds__(256)
k_gemm(const __half* __restrict__ X, const float* __restrict__ W,
       __half* __restrict__ H, int apply_act) {
    extern __shared__ __align__(16) char smem[];
    __half* Xs = (__half*)smem;                       // [128][XPADH]
    __half* Ws = (__half*)smem + 128 * XPADH;         // [128][XPADH]
    int tid = threadIdx.x;
    int warp = tid >> 5, lane = tid & 31;
    int wm = warp & 3, wn = warp >> 2;
    int n0 = blockIdx.x * 128;

    wmma::fragment<wmma::accumulator, 16, 16, 16, float> c[2][4];
#pragma unroll
    for (int i = 0; i < 2; i++)
#pragma unroll
        for (int j = 0; j < 4; j++) wmma::fill_fragment(c[i][j], 0.f);

    for (int k0 = 0; k0 < DIM; k0 += 32) {
        // stage X: 128 rows x 32 halves; 2 x uint4 (8 halves) per thread
#pragma unroll
        for (int it = 0; it < 2; it++) {
            int u = tid + it * 256;
            int row = u >> 2, c8 = (u & 3) * 8;
            uint4 v = *(const uint4*)(X + (size_t)(n0 + row) * DIM + k0 + c8);
            if (apply_act) {
                __half2* hp = (__half2*)&v;
#pragma unroll
                for (int q = 0; q < 4; q++) {
                    float2 f = __half22float2(hp[q]);
                    f.x = f.x > 0.f ? f.x : 0.01f * f.x;
                    f.y = f.y > 0.f ? f.y : 0.01f * f.y;
                    hp[q] = __floats2half2_rn(f.x, f.y);
                }
            }
            *(uint4*)(Xs + row * XPADH + c8) = v;
        }
        // stage W (fp32 -> fp16): 128 rows x 32 floats; 4 x float4 per thread
#pragma unroll
        for (int it = 0; it < 4; it++) {
            int u = tid + it * 256;
            int row = u >> 3, c4 = (u & 7) * 4;
            float4 w = *(const float4*)(W + (size_t)row * DIM + k0 + c4);
            __half2 w0 = __floats2half2_rn(w.x, w.y);
            __half2 w1 = __floats2half2_rn(w.z, w.w);
            uint2 uu;
            uu.x = *(unsigned*)&w0;
            uu.y = *(unsigned*)&w1;
            *(uint2*)(Ws + row * XPADH + c4) = uu;
        }
        __syncthreads();

#pragma unroll
        for (int kk = 0; kk < 32; kk += 16) {
            wmma::fragment<wmma::matrix_a, 16, 16, 16, __half, wmma::row_major> a[2];
            wmma::fragment<wmma::matrix_b, 16, 16, 16, __half, wmma::col_major> b[4];
#pragma unroll
            for (int i = 0; i < 2; i++)
                wmma::load_matrix_sync(a[i], Xs + (wm * 32 + i * 16) * XPADH + kk, XPADH);
#pragma unroll
            for (int j = 0; j < 4; j++)
                wmma::load_matrix_sync(b[j], Ws + (wn * 64 + j * 16) * XPADH + kk, XPADH);
#pragma unroll
            for (int i = 0; i < 2; i++)
#pragma unroll
                for (int j = 0; j < 4; j++)
                    wmma::mma_sync(c[i][j], a[i], b[j], c[i][j]);
        }
        __syncthreads();
    }

    // epilogue: per-warp smem region 32x64 fp32, convert to fp16, store
    float* epi = (float*)smem + warp * (32 * 64);
#pragma unroll
    for (int i = 0; i < 2; i++)
#pragma unroll
        for (int j = 0; j < 4; j++)
            wmma::store_matrix_sync(epi + i * 16 * 64 + j * 16, c[i][j], 64, wmma::mem_row_major);
    __syncwarp();
    {
        int row = lane;
        __half* hout = H + (size_t)(n0 + wm * 32 + row) * DIM + wn * 64;
        const float* src = epi + row * 64;
#pragma unroll
        for (int c0 = 0; c0 < 64; c0 += 8) {
            float4 f0 = *(const float4*)(src + c0);
            float4 f1 = *(const float4*)(src + c0 + 4);
            __half2 a0 = __floats2half2_rn(f0.x, f0.y);
            __half2 a1 = __floats2half2_rn(f0.z, f0.w);
            __half2 a2 = __floats2half2_rn(f1.x, f1.y);
            __half2 a3 = __floats2half2_rn(f1.z, f1.w);
            uint4 u;
            u.x = *(unsigned*)&a0; u.y = *(unsigned*)&a1;
            u.z = *(unsigned*)&a2; u.w = *(unsigned*)&a3;
            *(uint4*)(hout + c0) = u;
        }
    }
}

// ---------------- fused softmax + aggregate + next-layer dots -------------
// HALF-WARP per dst node: 16 lanes, dims [8*hl, 8*hl+8) as uint4 fp16 gathers.
// Single pass: softmax without max-subtraction (shift-invariant; logits are
// O(10), far below fp32 exp overflow at 88).
__global__ void k_layer(void* __restrict__ outp, const int* __restrict__ batch,
                        const float* __restrict__ as_in, const float* __restrict__ ad_in,
                        float* __restrict__ as_out, float* __restrict__ ad_out,
                        const float* __restrict__ vs_n, const float* __restrict__ vd_n,
                        int act_next, int mode) {
    int gt = blockIdx.x * blockDim.x + threadIdx.x;
    int d = gt >> 4, hl = gt & 15;
    if (d >= N_NODES) return;
    int row0 = g_row[d], row1 = g_row[d + 1];
    float ad_d = ad_in[d];

    float z = 0.f;
    float acc[8];
#pragma unroll
    for (int q = 0; q < 8; q++) acc[q] = 0.f;

    int i = row0;
    for (; i + 4 <= row1; i += 4) {
        int s0 = g_csrs[i], s1 = g_csrs[i + 1], s2 = g_csrs[i + 2], s3 = g_csrs[i + 3];
        uint4 u0 = ((const uint4*)(g_hh + (size_t)s0 * DIM))[hl];
        uint4 u1 = ((const uint4*)(g_hh + (size_t)s1 * DIM))[hl];
        uint4 u2 = ((const uint4*)(g_hh + (size_t)s2 * DIM))[hl];
        uint4 u3 = ((const uint4*)(g_hh + (size_t)s3 * DIM))[hl];
        float e0 = as_in[s0] + ad_d; e0 = e0 > 0.f ? e0 : 0.2f * e0;
        float e1 = as_in[s1] + ad_d; e1 = e1 > 0.f ? e1 : 0.2f * e1;
        float e2 = as_in[s2] + ad_d; e2 = e2 > 0.f ? e2 : 0.2f * e2;
        float e3 = as_in[s3] + ad_d; e3 = e3 > 0.f ? e3 : 0.2f * e3;
        float w0 = __expf(e0), w1 = __expf(e1);
        float w2 = __expf(e2), w3 = __expf(e3);
        z += (w0 + w1) + (w2 + w3);
        const unsigned* p0 = &u0.x;
        const unsigned* p1 = &u1.x;
        const unsigned* p2 = &u2.x;
        const unsigned* p3 = &u3.x;
#pragma unroll
        for (int q = 0; q < 4; q++) {
            float2 f0 = __half22float2(*(__half2*)&p0[q]);
            float2 f1 = __half22float2(*(__half2*)&p1[q]);
            float2 f2 = __half22float2(*(__half2*)&p2[q]);
            float2 f3 = __half22float2(*(__half2*)&p3[q]);
            acc[2*q]   = fmaf(w0, f0.x, fmaf(w1, f1.x, fmaf(w2, f2.x, fmaf(w3, f3.x, acc[2*q]))));
            acc[2*q+1] = fmaf(w0, f0.y, fmaf(w1, f1.y, fmaf(w2, f2.y, fmaf(w3, f3.y, acc[2*q+1]))));
        }
    }
    for (; i < row1; i++) {
        int s0 = g_csrs[i];
        uint4 u0 = ((const uint4*)(g_hh + (size_t)s0 * DIM))[hl];
        float e0 = as_in[s0] + ad_d; e0 = e0 > 0.f ? e0 : 0.2f * e0;
        float w0 = __expf(e0);
        z += w0;
        const unsigned* p0 = &u0.x;
#pragma unroll
        for (int q = 0; q < 4; q++) {
            float2 f0 = __half22float2(*(__half2*)&p0[q]);
            acc[2*q]   = fmaf(w0, f0.x, acc[2*q]);
            acc[2*q+1] = fmaf(w0, f0.y, acc[2*q+1]);
        }
    }
    float inv = 1.f / (z + 1e-16f);
#pragma unroll
    for (int q = 0; q < 8; q++) acc[q] *= inv;

    if (mode == 1) {
        float* p = (float*)outp + (size_t)batch[d] * DIM + hl * 8;
        asm volatile("red.global.add.v4.f32 [%0], {%1,%2,%3,%4};"
                     :: "l"(p), "f"(acc[0]), "f"(acc[1]), "f"(acc[2]), "f"(acc[3]) : "memory");
        asm volatile("red.global.add.v4.f32 [%0], {%1,%2,%3,%4};"
                     :: "l"(p + 4), "f"(acc[4]), "f"(acc[5]), "f"(acc[6]), "f"(acc[7]) : "memory");
    } else {
        __half2 h0 = __floats2half2_rn(acc[0], acc[1]);
        __half2 h1 = __floats2half2_rn(acc[2], acc[3]);
        __half2 h2 = __floats2half2_rn(acc[4], acc[5]);
        __half2 h3 = __floats2half2_rn(acc[6], acc[7]);
        uint4 u;
        u.x = *(unsigned*)&h0; u.y = *(unsigned*)&h1;
        u.z = *(unsigned*)&h2; u.w = *(unsigned*)&h3;
        ((uint4*)((__half*)outp + (size_t)d * DIM))[hl] = u;
        // next-layer attention dots from fp32 acc
        float t[8];
#pragma unroll
        for (int q = 0; q < 8; q++) {
            float v = acc[q];
            t[q] = act_next ? (v > 0.f ? v : 0.01f * v) : v;
        }
        float4 vs0 = ((const float4*)vs_n)[hl * 2];
        float4 vs1 = ((const float4*)vs_n)[hl * 2 + 1];
        float4 vd0 = ((const float4*)vd_n)[hl * 2];
        float4 vd1 = ((const float4*)vd_n)[hl * 2 + 1];
        float ps = t[0]*vs0.x + t[1]*vs0.y + t[2]*vs0.z + t[3]*vs0.w
                 + t[4]*vs1.x + t[5]*vs1.y + t[6]*vs1.z + t[7]*vs1.w;
        float pd = t[0]*vd0.x + t[1]*vd0.y + t[2]*vd0.z + t[3]*vd0.w
                 + t[4]*vd1.x + t[5]*vd1.y + t[6]*vd1.z + t[7]*vd1.w;
#pragma unroll
        for (int o = 8; o > 0; o >>= 1) {
            ps += __shfl_xor_sync(0xffffffffu, ps, o);
            pd += __shfl_xor_sync(0xffffffffu, pd, o);
        }
        if (hl == 0) { as_out[d] = ps; ad_out[d] = pd; }
    }
}

// ---------------- launch (single stream, R8 ordering) ---------------------
extern "C" void kernel_launch(void* const* d_in, const int* in_sizes, int n_in,
                              void* d_out, int out_size) {
    const float* x     = (const float*)d_in[0];
    const int*   ei    = (const int*)d_in[1];
    const int*   batch = (const int*)d_in[2];
    const float* W[3]   = {(const float*)d_in[3], (const float*)d_in[6], (const float*)d_in[9]};
    const float* As_[3] = {(const float*)d_in[4], (const float*)d_in[7], (const float*)d_in[10]};
    const float* Ad_[3] = {(const float*)d_in[5], (const float*)d_in[8], (const float*)d_in[11]};
    float* out = (float*)d_out;

    __half *xp, *b0, *b1, *hp;
    float *asA, *adA, *asB, *adB, *vsp, *vdp;
    cudaGetSymbolAddress((void**)&xp,  g_x);
    cudaGetSymbolAddress((void**)&b0,  g_b0);
    cudaGetSymbolAddress((void**)&b1,  g_b1);
    cudaGetSymbolAddress((void**)&hp,  g_hh);
    cudaGetSymbolAddress((void**)&asA, g_asA);
    cudaGetSymbolAddress((void**)&adA, g_adA);
    cudaGetSymbolAddress((void**)&asB, g_asB);
    cudaGetSymbolAddress((void**)&adB, g_adB);
    cudaGetSymbolAddress((void**)&vsp, g_vs);
    cudaGetSymbolAddress((void**)&vdp, g_vd);

    cudaFuncSetAttribute(k_gemm, cudaFuncAttributeMaxDynamicSharedMemorySize, GEMM_SMEM);

    // CSR build (per launch; capturable, no allocation)
    k_zero_cnt<<<(N_NODES + 255) / 256, 256>>>();
    k_prep_count<<<(E_TOT / 4 + 255) / 256, 256>>>(ei);
    k_scan<<<1, 1024>>>();
    k_fill<<<(E_TOT / 4 + 255) / 256, 256>>>();

    k_matvec<<<6, 128>>>(W[0], W[1], W[2], As_[0], Ad_[0], As_[1], Ad_[1], As_[2], Ad_[2]);
    k_copy_x<<<(N_NODES * 32 + 255) / 256, 256>>>(x);
    k_zero<<<(NUM_GRAPHS * DIM + 255) / 256, 256>>>(out, NUM_GRAPHS * DIM);

    // layer 0: dots set A -> writes b0 + set B (dots for layer 1, no act)
    k_gemm<<<NPAD / 128, 256, GEMM_SMEM>>>(xp, W[0], hp, 0);
    k_layer<<<(N_NODES * 16 + 255) / 256, 256>>>(b0, batch, asA, adA, asB, adB,
                                                 vsp + DIM, vdp + DIM, 0, 0);
    // layer 1: reads set B -> writes b1 + set A (dots for layer 2, act=leaky0.01)
    k_gemm<<<NPAD / 128, 256, GEMM_SMEM>>>(b0, W[1], hp, 0);
    k_layer<<<(N_NODES * 16 + 255) / 256, 256>>>(b1, batch, asB, adB, asA, adA,
                                                 vsp + 2 * DIM, vdp + 2 * DIM, 1, 0);
    // layer 2: GEMM applies act to input; reads set A; fused pool into out
    k_gemm<<<NPAD / 128, 256, GEMM_SMEM>>>(b1, W[2], hp, 1);
    k_layer<<<(N_NODES * 16 + 255) / 256, 256>>>(out, batch, asA, adA, nullptr, nullptr,
                                                 nullptr, nullptr, 0, 1);
}